// round 11
// baseline (speedup 1.0000x reference)
#include <cuda_runtime.h>
#include <float.h>

// Scratch (allocation-free). g_hist: zero at static init; select_mean_kernel
// re-zeroes it after consuming -> every graph replay sees zeros.
__device__ float g_ce[32768];
__device__ int   g_hist[65536];

// Monotone key transform (order-preserving float <-> uint).
__device__ __forceinline__ unsigned f2key(float f) {
    unsigned b = __float_as_uint(f);
    return (b & 0x80000000u) ? ~b : (b | 0x80000000u);
}
__device__ __forceinline__ float key2f(unsigned k) {
    unsigned b = (k & 0x80000000u) ? (k ^ 0x80000000u) : ~k;
    return __uint_as_float(b);
}

// ---------------------------------------------------------------------------
// Kernel 1: per-row cross entropy + dtype probe + fused 16-bit-key histogram.
// One warp per row; HBM-bound. The histogram atomic is one REDG per row over
// ~hundreds of bins (key>>16 spreads CE values at 2^-7 relative resolution),
// so no hot-address serialization (12-bit version in R7 had ~3 hot bins).
// ---------------------------------------------------------------------------
__global__ void __launch_bounds__(256)
ce_kernel(const float* __restrict__ x,
          const void* __restrict__ tgt,
          int N, int C)
{
    const int row  = blockIdx.x * 8 + (threadIdx.x >> 5);
    const int lane = threadIdx.x & 31;
    if (row >= N) return;

    const float4* rp = reinterpret_cast<const float4*>(x + (size_t)row * C);
    const int C4 = C >> 2;  // 250 for C=1000

    float4 v[8];
#pragma unroll
    for (int i = 0; i < 8; i++) {
        int c = lane + (i << 5);
        if (c < C4) v[i] = rp[c];
        else        v[i] = make_float4(-FLT_MAX, -FLT_MAX, -FLT_MAX, -FLT_MAX);
    }

    // Dtype probe (int64 targets in [0,C) have zero odd 32-bit words; L1-hot).
    const int* tw = reinterpret_cast<const int*>(tgt);
    int hiw = tw[2 * lane + 1];
    bool is64 = __all_sync(0xFFFFFFFFu, hiw == 0);

    float xt = 0.f;
    if (lane == 0) {
        long long t = is64 ? reinterpret_cast<const long long*>(tgt)[row]
                           : (long long)reinterpret_cast<const int*>(tgt)[row];
        if (t < 0)  t = 0;
        if (t >= C) t = C - 1;
        xt = x[(size_t)row * C + (int)t];
    }

    float m = -FLT_MAX;
#pragma unroll
    for (int i = 0; i < 8; i++)
        m = fmaxf(m, fmaxf(fmaxf(v[i].x, v[i].y), fmaxf(v[i].z, v[i].w)));
#pragma unroll
    for (int o = 16; o; o >>= 1)
        m = fmaxf(m, __shfl_xor_sync(0xFFFFFFFFu, m, o));

    float s0 = 0.f, s1 = 0.f, s2 = 0.f, s3 = 0.f;
#pragma unroll
    for (int i = 0; i < 8; i++) {
        s0 += __expf(v[i].x - m);
        s1 += __expf(v[i].y - m);
        s2 += __expf(v[i].z - m);
        s3 += __expf(v[i].w - m);
    }
    float s = (s0 + s1) + (s2 + s3);
#pragma unroll
    for (int o = 16; o; o >>= 1)
        s += __shfl_xor_sync(0xFFFFFFFFu, s, o);

    if (lane == 0) {
        float ce = m + __logf(s) - xt;
        g_ce[row] = ce;
        atomicAdd(&g_hist[f2key(ce) >> 16], 1);  // no return use -> RED
    }
}

// ---------------------------------------------------------------------------
// Kernel 2: single CTA, 1024 threads. Histogram is already built, so only:
//  (1) descending block-scan of 65536 bins -> bucket b + residual rank r
//  (2) one pass over g_ce (keys kept in registers), collect bucket-b
//      candidates to smem (~400 expected, cap 2048)
//  (3) warp 0: exact bit-serial select of rank-r among candidates' low 16
//      bits, while warps 1..31 re-zero g_hist for the next replay
//  (4) masked sum (key >= lam) from register keys; deterministic order.
// Tie semantics identical to the proven radix select (rank among multiset).
// ---------------------------------------------------------------------------
__global__ void __launch_bounds__(1024)
select_mean_kernel(float* __restrict__ out, int N, int k)
{
    const int tid  = threadIdx.x;
    const int lane = tid & 31;
    const int wid  = tid >> 5;
    const unsigned FULL = 0xFFFFFFFFu;

    __shared__ unsigned s_cand[2048];
    __shared__ int      s_ncand;
    __shared__ int      s_wsum[32];
    __shared__ int      s_woff[32];
    __shared__ int      s_b, s_r;
    __shared__ unsigned s_lam;
    __shared__ float    s_fsum[32];

    if (tid == 0) s_ncand = 0;

    // ---- (1) find bucket b containing descending rank k ----
    // Thread t owns 64 bins in descending order: [65535-64t .. 65535-64t-63].
    const int hi = 65535 - (tid << 6);
    int local = 0;
#pragma unroll 16
    for (int i = 0; i < 64; i++) local += g_hist[hi - i];

    // block scan (descending chunk order == thread order)
    int incl = local;
#pragma unroll
    for (int o = 1; o < 32; o <<= 1) {
        int v = __shfl_up_sync(FULL, incl, o);
        if (lane >= o) incl += v;
    }
    if (lane == 31) s_wsum[wid] = incl;
    __syncthreads();
    if (wid == 0) {
        int w = (lane < 32) ? s_wsum[lane] : 0;
        int wincl = w;
#pragma unroll
        for (int o = 1; o < 32; o <<= 1) {
            int v = __shfl_up_sync(FULL, wincl, o);
            if (lane >= o) wincl += v;
        }
        s_woff[lane] = wincl - w;  // exclusive warp offset
    }
    __syncthreads();
    int E = incl - local + s_woff[wid];  // elements in all higher bins

    if (k >= E && k < E + local) {       // exactly one thread hits
        int r = k - E;
        for (int i = 0; i < 64; i++) {
            int c = g_hist[hi - i];
            if (r < c) { s_b = hi - i; s_r = r; break; }
            r -= c;
        }
    }
    __syncthreads();
    const int b = s_b;

    // ---- (2) pass over g_ce; keys in registers; collect bucket-b candidates
    const float4* ce4 = reinterpret_cast<const float4*>(g_ce);
    const int N4 = N >> 2;
    unsigned key[32];
#pragma unroll
    for (int j = 0; j < 8; j++) {
        int bb = tid + (j << 10);
        float4 v;
        if (bb < N4) v = ce4[bb];
        else         v = make_float4(-FLT_MAX, -FLT_MAX, -FLT_MAX, -FLT_MAX);
        key[4 * j + 0] = f2key(v.x);
        key[4 * j + 1] = f2key(v.y);
        key[4 * j + 2] = f2key(v.z);
        key[4 * j + 3] = f2key(v.w);
    }
#pragma unroll
    for (int i = 0; i < 32; i++) {
        if ((int)(key[i] >> 16) == b) {
            int pos = atomicAdd(&s_ncand, 1);
            if (pos < 2048) s_cand[pos] = key[i];
        }
    }
    __syncthreads();
    const int ncand = (s_ncand < 2048) ? s_ncand : 2048;

    // ---- (3) warp 0: bit-serial rank-s_r select among candidates' low bits;
    //          warps 1..31: re-zero g_hist for the next graph replay.
    if (wid == 0) {
        int rank = s_r;
        // my candidates: indices lane, lane+32, ... ; active mask bit i
        unsigned long long act = 0ull;
        int nmy = 0;
        for (int i = 0; lane + 32 * i < ncand && i < 64; i++) { act |= (1ull << i); nmy = i + 1; }

        unsigned lam_low = 0u;
#pragma unroll
        for (int bit = 15; bit >= 0; bit--) {
            const unsigned bm = 1u << bit;
            int c = 0;
            for (int i = 0; i < nmy; i++)
                if ((act >> i) & 1ull)
                    if (s_cand[lane + 32 * i] & bm) c++;
            int tot = __reduce_add_sync(FULL, c);  // same on all lanes
            if (rank < tot) {
                lam_low |= bm;  // keep only candidates with this bit set
                for (int i = 0; i < nmy; i++)
                    if (((act >> i) & 1ull) && !(s_cand[lane + 32 * i] & bm))
                        act &= ~(1ull << i);
            } else {
                rank -= tot;    // keep only candidates with this bit clear
                for (int i = 0; i < nmy; i++)
                    if (((act >> i) & 1ull) && (s_cand[lane + 32 * i] & bm))
                        act &= ~(1ull << i);
            }
        }
        if (lane == 0) s_lam = ((unsigned)b << 16) | lam_low;
    } else {
        // zero g_hist: threads 32..1023 cover 16384 uint4 rows; thread 32+t
        // writes rows [t*16.5...] -> use stride mapping over 992 threads.
        uint4* h4 = reinterpret_cast<uint4*>(g_hist);
        const uint4 z = make_uint4(0, 0, 0, 0);
        for (int i = tid - 32; i < 16384; i += 992) h4[i] = z;
    }
    __syncthreads();
    const unsigned lam = s_lam;  // exact key of sorted_desc[k]

    // ---- (4) masked mean: keep key >= lam (ties kept). Deterministic order.
    float sum = 0.f;
#pragma unroll
    for (int i = 0; i < 32; i++)
        if (key[i] >= lam) sum += key2f(key[i]);
#pragma unroll
    for (int o = 16; o; o >>= 1)
        sum += __shfl_xor_sync(FULL, sum, o);
    if (lane == 0) s_fsum[wid] = sum;
    __syncthreads();

    if (tid == 0) {
        double tot = 0.0;
#pragma unroll
        for (int w = 0; w < 32; w++) tot += (double)s_fsum[w];
        out[0] = (float)(tot / (double)N);
    }
}

// ---------------------------------------------------------------------------
extern "C" void kernel_launch(void* const* d_in, const int* in_sizes, int n_in,
                              void* d_out, int out_size)
{
    int li = 0, ti = 1;
    if (n_in >= 2 && in_sizes[1] > in_sizes[0]) { li = 1; ti = 0; }

    const float* x   = (const float*)d_in[li];
    const void*  tgt = d_in[ti];
    float* out = (float*)d_out;

    const int N = in_sizes[ti];            // 32768
    const int C = in_sizes[li] / N;        // 1000
    const int k = (int)((double)N * 0.3);  // 9830

    const int warps_per_block = 8;
    const int blocks = (N + warps_per_block - 1) / warps_per_block;
    ce_kernel<<<blocks, 256>>>(x, tgt, N, C);

    select_mean_kernel<<<1, 1024>>>(out, N, k);
}

// round 12
// speedup vs baseline: 1.1355x; 1.1355x over previous
#include <cuda_runtime.h>
#include <float.h>

// Scratch (allocation-free). g_hist: zero at static init; select_mean_kernel
// re-zeroes it after consuming -> every graph replay sees zeros.
__device__ float g_ce[32768];
__device__ int   g_hist[65536];

// Monotone key transform (order-preserving float <-> uint).
__device__ __forceinline__ unsigned f2key(float f) {
    unsigned b = __float_as_uint(f);
    return (b & 0x80000000u) ? ~b : (b | 0x80000000u);
}
__device__ __forceinline__ float key2f(unsigned k) {
    unsigned b = (k & 0x80000000u) ? (k ^ 0x80000000u) : ~k;
    return __uint_as_float(b);
}

// ---------------------------------------------------------------------------
// Kernel 1: per-row cross entropy + dtype probe + fused 16-bit-key histogram.
// One warp per row; HBM-bound. key>>16 spreads CE values over ~hundreds of
// bins -> the one REDG per row is contention-free (verified R11: ce at floor).
// ---------------------------------------------------------------------------
__global__ void __launch_bounds__(256)
ce_kernel(const float* __restrict__ x,
          const void* __restrict__ tgt,
          int N, int C)
{
    const int row  = blockIdx.x * 8 + (threadIdx.x >> 5);
    const int lane = threadIdx.x & 31;
    if (row >= N) return;

    const float4* rp = reinterpret_cast<const float4*>(x + (size_t)row * C);
    const int C4 = C >> 2;  // 250 for C=1000

    float4 v[8];
#pragma unroll
    for (int i = 0; i < 8; i++) {
        int c = lane + (i << 5);
        if (c < C4) v[i] = rp[c];
        else        v[i] = make_float4(-FLT_MAX, -FLT_MAX, -FLT_MAX, -FLT_MAX);
    }

    // Dtype probe (int64 targets in [0,C) have zero odd 32-bit words; L1-hot).
    const int* tw = reinterpret_cast<const int*>(tgt);
    int hiw = tw[2 * lane + 1];
    bool is64 = __all_sync(0xFFFFFFFFu, hiw == 0);

    float xt = 0.f;
    if (lane == 0) {
        long long t = is64 ? reinterpret_cast<const long long*>(tgt)[row]
                           : (long long)reinterpret_cast<const int*>(tgt)[row];
        if (t < 0)  t = 0;
        if (t >= C) t = C - 1;
        xt = x[(size_t)row * C + (int)t];
    }

    float m = -FLT_MAX;
#pragma unroll
    for (int i = 0; i < 8; i++)
        m = fmaxf(m, fmaxf(fmaxf(v[i].x, v[i].y), fmaxf(v[i].z, v[i].w)));
#pragma unroll
    for (int o = 16; o; o >>= 1)
        m = fmaxf(m, __shfl_xor_sync(0xFFFFFFFFu, m, o));

    float s0 = 0.f, s1 = 0.f, s2 = 0.f, s3 = 0.f;
#pragma unroll
    for (int i = 0; i < 8; i++) {
        s0 += __expf(v[i].x - m);
        s1 += __expf(v[i].y - m);
        s2 += __expf(v[i].z - m);
        s3 += __expf(v[i].w - m);
    }
    float s = (s0 + s1) + (s2 + s3);
#pragma unroll
    for (int o = 16; o; o >>= 1)
        s += __shfl_xor_sync(0xFFFFFFFFu, s, o);

    if (lane == 0) {
        float ce = m + __logf(s) - xt;
        g_ce[row] = ce;
        atomicAdd(&g_hist[f2key(ce) >> 16], 1);  // no return use -> RED
    }
}

// ---------------------------------------------------------------------------
// Kernel 2: single CTA, 512 threads (16 warps), COALESCED histogram access.
//  (1) warp w owns contiguous bins [65535-4096(w+1)+1 .. 65535-4096w];
//      lanes read uint4-coalesced; warp totals.
//  (2) warp 0 descending-scans 16 totals -> hit warp W + residual r1.
//  (3) warp W re-reads its block (L2-hot, coalesced per lane chunk), keeps
//      32 dword-sums in REGISTERS, scans lanes, walks registers -> exact
//      bin s_b + residual s_r. One final uint4 reload only.
//  (4) key pass over g_ce (64 keys/thread in regs); bucket-b candidates
//      to smem (expected ~tens; cap 2048).
//  (5) warp 0: bit-serial rank select on candidates' low 16 bits;
//      warps 1..15 re-zero g_hist (256 KB, coalesced stores).
//  (6) masked sum (key >= lam) from register keys; deterministic order.
// ---------------------------------------------------------------------------
__global__ void __launch_bounds__(512)
select_mean_kernel(float* __restrict__ out, int N, int k)
{
    const int tid  = threadIdx.x;
    const int lane = tid & 31;
    const int wid  = tid >> 5;
    const unsigned FULL = 0xFFFFFFFFu;

    __shared__ unsigned s_cand[2048];
    __shared__ int      s_ncand;
    __shared__ int      s_wtot[16];
    __shared__ int      s_W, s_r1;
    __shared__ int      s_b, s_r;
    __shared__ unsigned s_lam;
    __shared__ float    s_fsum[16];

    if (tid == 0) s_ncand = 0;

    const uint4* h4 = reinterpret_cast<const uint4*>(g_hist);

    // ---- (1) coalesced block totals: warp w owns h4[16384-1024(w+1) .. ) ----
    {
        const int B4 = 16384 - 1024 * (wid + 1);
        unsigned csum = 0;
#pragma unroll
        for (int j = 0; j < 32; j++) {
            uint4 q = h4[B4 + lane + 32 * j];
            csum += q.x + q.y + q.z + q.w;
        }
        csum = __reduce_add_sync(FULL, csum);
        if (lane == 0) s_wtot[wid] = (int)csum;
    }
    __syncthreads();

    // ---- (2) warp 0: descending scan of 16 warp totals ----
    if (wid == 0 && lane < 16) {
        int tot = s_wtot[lane];
        int incl = tot;
#pragma unroll
        for (int o = 1; o < 16; o <<= 1) {
            int v = __shfl_up_sync(0xFFFFu, incl, o);
            if (lane >= o) incl += v;
        }
        int E = incl - tot;  // keys in bins above warp-lane's block
        if (k >= E && k < E + tot) { s_W = lane; s_r1 = k - E; }
    }
    __syncthreads();
    const int W = s_W;

    // ---- (3) warp W: locate exact bin; register-resident walk ----
    if (wid == W) {
        // lane l owns descending 128-bin chunk; ascending h4 range:
        const int s4 = 16384 - 1024 * W - 32 * (lane + 1);  // 32 uint4
        unsigned d[32];
        unsigned csum = 0;
#pragma unroll
        for (int j = 0; j < 32; j++) {
            uint4 q = h4[s4 + j];
            d[j] = q.x + q.y + q.z + q.w;
            csum += d[j];
        }
        int incl = (int)csum;
#pragma unroll
        for (int o = 1; o < 32; o <<= 1) {
            int v = __shfl_up_sync(FULL, incl, o);
            if (lane >= o) incl += v;
        }
        int E2 = incl - (int)csum;
        int r1 = s_r1;
        if (r1 >= E2 && r1 < E2 + (int)csum) {   // exactly one lane
            int r2 = r1 - E2;
            // walk dword-sums descending (j=31 = highest bins), registers only
#pragma unroll
            for (int j = 31; j >= 0; j--) {
                if (r2 < (int)d[j]) {
                    uint4 q = h4[s4 + j];      // single L2-hot reload
                    int bin;
                    if      (r2 < (int)q.w)                     { bin = 4*(s4+j)+3; }
                    else if (r2 < (int)(q.w+q.z))               { bin = 4*(s4+j)+2; r2 -= q.w; }
                    else if (r2 < (int)(q.w+q.z+q.y))           { bin = 4*(s4+j)+1; r2 -= q.w+q.z; }
                    else                                        { bin = 4*(s4+j)+0; r2 -= q.w+q.z+q.y; }
                    s_b = bin; s_r = r2;
                    break;
                }
                r2 -= (int)d[j];
            }
        }
    }
    __syncthreads();
    const int b = s_b;

    // ---- (4) key pass: 64 keys/thread in registers; collect candidates ----
    const float4* ce4 = reinterpret_cast<const float4*>(g_ce);
    const int N4 = N >> 2;
    unsigned key[64];
#pragma unroll
    for (int j = 0; j < 16; j++) {
        int bb = tid + (j << 9);
        float4 v;
        if (bb < N4) v = ce4[bb];
        else         v = make_float4(-FLT_MAX, -FLT_MAX, -FLT_MAX, -FLT_MAX);
        key[4 * j + 0] = f2key(v.x);
        key[4 * j + 1] = f2key(v.y);
        key[4 * j + 2] = f2key(v.z);
        key[4 * j + 3] = f2key(v.w);
    }
#pragma unroll
    for (int i = 0; i < 64; i++) {
        if ((int)(key[i] >> 16) == b) {
            int pos = atomicAdd(&s_ncand, 1);
            if (pos < 2048) s_cand[pos] = key[i];
        }
    }
    __syncthreads();
    const int ncand = (s_ncand < 2048) ? s_ncand : 2048;

    // ---- (5) warp 0: low-16 bit-serial select; others zero g_hist ----
    if (wid == 0) {
        int rank = s_r;
        unsigned long long act = 0ull;
        int nmy = 0;
        for (int i = 0; lane + 32 * i < ncand && i < 64; i++) { act |= (1ull << i); nmy = i + 1; }

        unsigned lam_low = 0u;
#pragma unroll
        for (int bit = 15; bit >= 0; bit--) {
            const unsigned bm = 1u << bit;
            int c = 0;
            for (int i = 0; i < nmy; i++)
                if ((act >> i) & 1ull)
                    if (s_cand[lane + 32 * i] & bm) c++;
            int tot = __reduce_add_sync(FULL, c);
            if (rank < tot) {
                lam_low |= bm;
                for (int i = 0; i < nmy; i++)
                    if (((act >> i) & 1ull) && !(s_cand[lane + 32 * i] & bm))
                        act &= ~(1ull << i);
            } else {
                rank -= tot;
                for (int i = 0; i < nmy; i++)
                    if (((act >> i) & 1ull) && (s_cand[lane + 32 * i] & bm))
                        act &= ~(1ull << i);
            }
        }
        if (lane == 0) s_lam = ((unsigned)b << 16) | lam_low;
    } else {
        // zero 16384 uint4 with 480 threads, coalesced
        uint4* hz = reinterpret_cast<uint4*>(g_hist);
        const uint4 z = make_uint4(0, 0, 0, 0);
        for (int i = tid - 32; i < 16384; i += 480) hz[i] = z;
    }
    __syncthreads();
    const unsigned lam = s_lam;  // exact key of sorted_desc[k]

    // ---- (6) masked mean: keep key >= lam (ties kept) ----
    float sum = 0.f;
#pragma unroll
    for (int i = 0; i < 64; i++)
        if (key[i] >= lam) sum += key2f(key[i]);
#pragma unroll
    for (int o = 16; o; o >>= 1)
        sum += __shfl_xor_sync(FULL, sum, o);
    if (lane == 0) s_fsum[wid] = sum;
    __syncthreads();

    if (tid == 0) {
        double tot = 0.0;
#pragma unroll
        for (int w = 0; w < 16; w++) tot += (double)s_fsum[w];
        out[0] = (float)(tot / (double)N);
    }
}

// ---------------------------------------------------------------------------
extern "C" void kernel_launch(void* const* d_in, const int* in_sizes, int n_in,
                              void* d_out, int out_size)
{
    int li = 0, ti = 1;
    if (n_in >= 2 && in_sizes[1] > in_sizes[0]) { li = 1; ti = 0; }

    const float* x   = (const float*)d_in[li];
    const void*  tgt = d_in[ti];
    float* out = (float*)d_out;

    const int N = in_sizes[ti];            // 32768
    const int C = in_sizes[li] / N;        // 1000
    const int k = (int)((double)N * 0.3);  // 9830

    const int warps_per_block = 8;
    const int blocks = (N + warps_per_block - 1) / warps_per_block;
    ce_kernel<<<blocks, 256>>>(x, tgt, N, C);

    select_mean_kernel<<<1, 512>>>(out, N, k);
}

// round 13
// speedup vs baseline: 2.1390x; 1.8837x over previous
#include <cuda_runtime.h>
#include <float.h>

// Scratch for per-sample CE losses (allocation-free: __device__ global).
__device__ float g_ce[32768];

// Monotone key transform (order-preserving float -> uint).
__device__ __forceinline__ unsigned f2key(float f) {
    unsigned b = __float_as_uint(f);
    return (b & 0x80000000u) ? ~b : (b | 0x80000000u);
}

// ---------------------------------------------------------------------------
// Kernel 1: per-row cross entropy + inline target-dtype detection.
// One warp per row, row (C<=1024 floats) in registers. HBM-bound ~22 us.
// Proven clean version (R5): no global atomics.
// ---------------------------------------------------------------------------
__global__ void __launch_bounds__(256)
ce_kernel(const float* __restrict__ x,
          const void* __restrict__ tgt,
          int N, int C)
{
    const int row  = blockIdx.x * 8 + (threadIdx.x >> 5);
    const int lane = threadIdx.x & 31;
    if (row >= N) return;

    const float4* rp = reinterpret_cast<const float4*>(x + (size_t)row * C);
    const int C4 = C >> 2;  // 250 for C=1000

    float4 v[8];
#pragma unroll
    for (int i = 0; i < 8; i++) {
        int c = lane + (i << 5);
        if (c < C4) v[i] = rp[c];
        else        v[i] = make_float4(-FLT_MAX, -FLT_MAX, -FLT_MAX, -FLT_MAX);
    }

    // Dtype probe (int64 targets in [0,C) have zero odd 32-bit words; L1-hot).
    const int* tw = reinterpret_cast<const int*>(tgt);
    int hiw = tw[2 * lane + 1];
    bool is64 = __all_sync(0xFFFFFFFFu, hiw == 0);

    float xt = 0.f;
    if (lane == 0) {
        long long t = is64 ? reinterpret_cast<const long long*>(tgt)[row]
                           : (long long)reinterpret_cast<const int*>(tgt)[row];
        if (t < 0)  t = 0;
        if (t >= C) t = C - 1;
        xt = x[(size_t)row * C + (int)t];
    }

    float m = -FLT_MAX;
#pragma unroll
    for (int i = 0; i < 8; i++)
        m = fmaxf(m, fmaxf(fmaxf(v[i].x, v[i].y), fmaxf(v[i].z, v[i].w)));
#pragma unroll
    for (int o = 16; o; o >>= 1)
        m = fmaxf(m, __shfl_xor_sync(0xFFFFFFFFu, m, o));

    float s0 = 0.f, s1 = 0.f, s2 = 0.f, s3 = 0.f;
#pragma unroll
    for (int i = 0; i < 8; i++) {
        s0 += __expf(v[i].x - m);
        s1 += __expf(v[i].y - m);
        s2 += __expf(v[i].z - m);
        s3 += __expf(v[i].w - m);
    }
    float s = (s0 + s1) + (s2 + s3);
#pragma unroll
    for (int o = 16; o; o >>= 1)
        s += __shfl_xor_sync(0xFFFFFFFFu, s, o);

    if (lane == 0)
        g_ce[row] = m + __logf(s) - xt;
}

// In-place 32x32 bit transpose (Hacker's Delight).
__device__ __forceinline__ void bit_transpose32(unsigned m[32])
{
#pragma unroll
    for (int st = 0; st < 5; st++) {
        const int j = 16 >> st;
        const unsigned msk = (st == 0) ? 0x0000FFFFu :
                             (st == 1) ? 0x00FF00FFu :
                             (st == 2) ? 0x0F0F0F0Fu :
                             (st == 3) ? 0x33333333u : 0x55555555u;
#pragma unroll
        for (int kk = 0; kk < 32; kk++) {
            if ((kk & j) == 0) {
                unsigned t2 = (m[kk] ^ (m[kk + j] >> j)) & msk;
                m[kk]     ^= t2;
                m[kk + j] ^= (t2 << j);
            }
        }
    }
}

// ---------------------------------------------------------------------------
// Kernel 2: single CTA, 512 threads x 64 keys in TWO transposed banks
// (mA[32], mB[32]). 128-reg/thread budget at 512 threads -> NO SPILLS
// (the R6/R9 64-reg saturation is what made 16-way rounds slow).
// 8 rounds of 16-way MSB-first radix; counts via popc on bitplanes, packed
// 2x16-bit REDUX (warp field <= 2048, block field <= 32768). Exact tie
// semantics of sorted_desc[k]. Masked sum reloads g_ce (L2-hot).
// ---------------------------------------------------------------------------
__global__ void __launch_bounds__(512)
select_mean_kernel(float* __restrict__ out, int N, int k)
{
    const int tid  = threadIdx.x;
    const int lane = tid & 31;
    const int wid  = tid >> 5;
    const unsigned FULL = 0xFFFFFFFFu;

    const float4* ce4 = reinterpret_cast<const float4*>(g_ce);
    const int N4 = N >> 2;  // 8192; 512 threads x 16 float4 covers exactly

    // Load 64 keys: bank A = chunks 0..7, bank B = chunks 8..15.
    unsigned mA[32], mB[32];
#pragma unroll
    for (int j = 0; j < 8; j++) {
        int b = tid + (j << 9);
        float4 v = (b < N4) ? ce4[b]
                            : make_float4(-FLT_MAX, -FLT_MAX, -FLT_MAX, -FLT_MAX);
        mA[4 * j + 0] = f2key(v.x);
        mA[4 * j + 1] = f2key(v.y);
        mA[4 * j + 2] = f2key(v.z);
        mA[4 * j + 3] = f2key(v.w);
    }
#pragma unroll
    for (int j = 0; j < 8; j++) {
        int b = tid + ((j + 8) << 9);
        float4 v = (b < N4) ? ce4[b]
                            : make_float4(-FLT_MAX, -FLT_MAX, -FLT_MAX, -FLT_MAX);
        mB[4 * j + 0] = f2key(v.x);
        mB[4 * j + 1] = f2key(v.y);
        mB[4 * j + 2] = f2key(v.z);
        mB[4 * j + 3] = f2key(v.w);
    }

    bit_transpose32(mA);   // mA[idx] = key-bit (31-idx) across bank-A slots
    bit_transpose32(mB);

    __shared__ unsigned s_cnt[8 * 16];   // [packed-pair][warp]
    __shared__ int      s_sel;
    __shared__ float    s_fsum[16];

    unsigned amaskA = FULL, amaskB = FULL;  // active slots per bank
    unsigned lamkey = 0u;
    int rank = k;   // consumed by warp 0 / lane 0 only

#pragma unroll
    for (int r = 0; r < 8; r++) {
        const unsigned a0 = mA[4 * r + 0], a1 = mA[4 * r + 1];
        const unsigned a2 = mA[4 * r + 2], a3 = mA[4 * r + 3];
        const unsigned b0 = mB[4 * r + 0], b1 = mB[4 * r + 1];
        const unsigned b2 = mB[4 * r + 2], b3 = mB[4 * r + 3];

        unsigned c[16];
#pragma unroll
        for (int j = 0; j < 16; j++) {
            unsigned sA = amaskA, sB = amaskB;
            sA &= (j & 8) ? a0 : ~a0;  sB &= (j & 8) ? b0 : ~b0;
            sA &= (j & 4) ? a1 : ~a1;  sB &= (j & 4) ? b1 : ~b1;
            sA &= (j & 2) ? a2 : ~a2;  sB &= (j & 2) ? b2 : ~b2;
            sA &= (j & 1) ? a3 : ~a3;  sB &= (j & 1) ? b3 : ~b3;
            c[j] = (unsigned)(__popc(sA) + __popc(sB));   // <= 64
        }
#pragma unroll
        for (int p = 0; p < 8; p++) {
            unsigned packed = c[2 * p] | (c[2 * p + 1] << 16);
            packed = __reduce_add_sync(FULL, packed);     // warp field <= 2048
            if (lane == p) s_cnt[p * 16 + wid] = packed;
        }
        __syncthreads();

        if (wid == 0) {
            unsigned t[8];
#pragma unroll
            for (int p = 0; p < 8; p++)
                t[p] = __reduce_add_sync(FULL, (lane < 16) ? s_cnt[p * 16 + lane] : 0u);
            if (lane == 0) {
                int bc[16];
#pragma unroll
                for (int p = 0; p < 8; p++) {
                    bc[2 * p]     = (int)(t[p] & 0xFFFFu);
                    bc[2 * p + 1] = (int)(t[p] >> 16);
                }
                int chosen = 0;
                bool found = false;
#pragma unroll
                for (int q = 15; q >= 1; q--) {
                    if (!found) {
                        if (rank < bc[q]) { chosen = q; found = true; }
                        else               rank -= bc[q];
                    }
                }
                s_sel = chosen;
            }
        }
        __syncthreads();

        const int j = s_sel;
        {
            unsigned sA = amaskA, sB = amaskB;
            sA &= (j & 8) ? a0 : ~a0;  sB &= (j & 8) ? b0 : ~b0;
            sA &= (j & 4) ? a1 : ~a1;  sB &= (j & 4) ? b1 : ~b1;
            sA &= (j & 2) ? a2 : ~a2;  sB &= (j & 2) ? b2 : ~b2;
            sA &= (j & 1) ? a3 : ~a3;  sB &= (j & 1) ? b3 : ~b3;
            amaskA = sA; amaskB = sB;
        }
        lamkey |= ((unsigned)j) << (28 - 4 * r);
        // No third barrier needed: round r+1's s_cnt writes happen only after
        // this barrier, and warp 0 finished reading s_cnt before writing s_sel.
    }

    // Masked mean: reload values (L2-hot) and keep f2key(v) >= lamkey
    // (ties kept, matching `ce < lam -> 0`). Deterministic order.
    float sum = 0.f;
#pragma unroll
    for (int j = 0; j < 16; j++) {
        int b = tid + (j << 9);
        if (b < N4) {
            float4 v = ce4[b];
            if (f2key(v.x) >= lamkey) sum += v.x;
            if (f2key(v.y) >= lamkey) sum += v.y;
            if (f2key(v.z) >= lamkey) sum += v.z;
            if (f2key(v.w) >= lamkey) sum += v.w;
        }
    }
#pragma unroll
    for (int o = 16; o; o >>= 1)
        sum += __shfl_xor_sync(FULL, sum, o);
    if (lane == 0) s_fsum[wid] = sum;
    __syncthreads();

    if (tid == 0) {
        double tot = 0.0;
#pragma unroll
        for (int w = 0; w < 16; w++) tot += (double)s_fsum[w];
        out[0] = (float)(tot / (double)N);
    }
}

// ---------------------------------------------------------------------------
extern "C" void kernel_launch(void* const* d_in, const int* in_sizes, int n_in,
                              void* d_out, int out_size)
{
    int li = 0, ti = 1;
    if (n_in >= 2 && in_sizes[1] > in_sizes[0]) { li = 1; ti = 0; }

    const float* x   = (const float*)d_in[li];
    const void*  tgt = d_in[ti];
    float* out = (float*)d_out;

    const int N = in_sizes[ti];            // 32768
    const int C = in_sizes[li] / N;        // 1000
    const int k = (int)((double)N * 0.3);  // 9830

    const int warps_per_block = 8;
    const int blocks = (N + warps_per_block - 1) / warps_per_block;
    ce_kernel<<<blocks, 256>>>(x, tgt, N, C);

    select_mean_kernel<<<1, 512>>>(out, N, k);
}